// round 7
// baseline (speedup 1.0000x reference)
#include <cuda_runtime.h>

#define NPTS    25600     // 128 batches * 200 cells
#define XROW    407       // 2 + 400 + 5
#define NSTEPS  50
#define DTF     0.001f
#define NBLK    148
#define TPB     352       // 11 warps; 176 pairs/block
#define NP      176       // pairs per block (stash lane count)
#define PAIRS_ACTIVE 173  // ceil(25600/148)

// ---- weights in constant memory (warp-uniform -> LDCU path, off L1tex) ----
__constant__ float cw0[32];    // (16,2)
__constant__ float cw1[512];   // (32,16)
__constant__ float cw2[1024];  // (32,32)
__constant__ float cw3[512];   // (16,32)
__constant__ float cw4[16];    // (1,16)
__constant__ float cb0[16], cb1[32], cb2[32], cb3[16], cwt[4];

// dynamic smem = per-pair activation stash only
// rows: H1=0..15, H2=16..47, H3=48..79, G4=80..95, G3=96..127  (row stride NP)
#define SMEM_FLOATS (128 * NP)        // 22528
#define SMEM_BYTES  (SMEM_FLOATS * 4) // 90112

__device__ __forceinline__ float softplus_f(float z) {
    float e = __expf(-fabsf(z));
    return fmaxf(z, 0.0f) + __logf(1.0f + e);
}
__device__ __forceinline__ float sig_only(float z) {
    float e = __expf(-fabsf(z));
    float u = 1.0f + e;
    float r;
    asm("rcp.approx.f32 %0, %1;" : "=f"(r) : "f"(u));
    return (z >= 0.0f) ? r : e * r;
}
__device__ __forceinline__ float sig_from_h(float h) {   // sigmoid(z) = 1 - e^{-softplus(z)}
    return 1.0f - __expf(-h);
}

__global__ void __launch_bounds__(TPB, 1)
phinn_kernel(const float* __restrict__ x, float* __restrict__ out)
{
    extern __shared__ float sm[];
    const int tid  = threadIdx.x;
    const int pid  = tid >> 1;
    const int half = tid & 1;

    float* __restrict__ ST = sm + pid;   // this pair's stash lane

    const int  preal  = blockIdx.x * PAIRS_ACTIVE + pid;
    const bool active = (pid < PAIRS_ACTIVE) && (preal < NPTS);
    const int  p  = active ? preal : (NPTS - 1);      // clamp for dummies
    const int  b  = p / 200;
    const int  c  = p - b * 200;
    const float* xb = x + b * XROW;

    float y0 = xb[2 + 2 * c];
    float y1 = xb[3 + 2 * c];
    float ts = xb[0];
    const float sp0 = xb[402];
    const float tA0 = fmaf(xb[403], cwt[0], xb[404] * cwt[1]);
    const float tA1 = fmaf(xb[403], cwt[2], xb[404] * cwt[3]);
    const float tB0 = fmaf(xb[405], cwt[0], xb[406] * cwt[1]);
    const float tB1 = fmaf(xb[405], cwt[2], xb[406] * cwt[3]);

    float v[32];     // full activation / gradient vector
    float a[16];     // own-half accumulators
    float g[16];     // full g4

    #pragma unroll 1
    for (int it = 0; it < NSTEPS; ++it) {
        const bool  early = (ts < sp0);
        const float ti0 = early ? tA0 : tB0;
        const float ti1 = early ? tA1 : tB1;

        // ---- L1: own 8 of 16 ----
        #pragma unroll
        for (int j = 0; j < 8; ++j) {
            int o = 8 * half + j;
            float z = fmaf(cw0[2*o], y0, fmaf(cw0[2*o + 1], y1, cb0[o]));
            ST[o * NP] = softplus_f(z);
        }
        __syncwarp();
        #pragma unroll
        for (int i = 0; i < 16; ++i) v[i] = ST[i * NP];          // full h1

        // ---- L2: own 16 of 32 ----
        #pragma unroll
        for (int j = 0; j < 16; ++j) {
            int o = 16 * half + j;
            float z = cb1[o];
            const float* wr = cw1 + o * 16;
            #pragma unroll
            for (int q = 0; q < 16; ++q) z = fmaf(wr[q], v[q], z);
            ST[(16 + o) * NP] = softplus_f(z);
        }
        __syncwarp();
        #pragma unroll
        for (int i = 0; i < 32; ++i) v[i] = ST[(16 + i) * NP];   // full h2

        // ---- L3: own 16 of 32 ----
        #pragma unroll
        for (int j = 0; j < 16; ++j) {
            int o = 16 * half + j;
            float z = cb2[o];
            const float* wr = cw2 + o * 32;
            #pragma unroll
            for (int q = 0; q < 32; ++q) z = fmaf(wr[q], v[q], z);
            ST[(48 + o) * NP] = softplus_f(z);
        }
        __syncwarp();
        #pragma unroll
        for (int i = 0; i < 32; ++i) v[i] = ST[(48 + i) * NP];   // full h3

        // ---- L4: own 8 of 16; g4 = sigmoid(z4)*w4 ----
        #pragma unroll
        for (int j = 0; j < 8; ++j) {
            int o = 8 * half + j;
            float z = cb3[o];
            const float* wr = cw3 + o * 32;
            #pragma unroll
            for (int q = 0; q < 32; ++q) z = fmaf(wr[q], v[q], z);
            ST[(80 + o) * NP] = sig_only(z) * cw4[o];
        }
        __syncwarp();
        #pragma unroll
        for (int o = 0; o < 16; ++o) g[o] = ST[(80 + o) * NP];   // full g4

        // ---- g3 (own 16 of 32): (w3^T g4) * sig(h3 own) ----
        #pragma unroll
        for (int j = 0; j < 16; ++j) a[j] = 0.0f;
        #pragma unroll
        for (int o = 0; o < 16; ++o) {
            const float go = g[o];
            const float* wr = cw3 + o * 32 + 16 * half;
            #pragma unroll
            for (int q = 0; q < 16; ++q) a[q] = fmaf(wr[q], go, a[q]);
        }
        #pragma unroll
        for (int j = 0; j < 16; ++j) {
            int i = 16 * half + j;
            ST[(96 + i) * NP] = a[j] * sig_from_h(ST[(48 + i) * NP]);
        }
        __syncwarp();
        #pragma unroll
        for (int i = 0; i < 32; ++i) v[i] = ST[(96 + i) * NP];   // full g3

        // ---- g2 (own 16 of 32): (w2^T g3) * sig(h2 own)  -> reuse H3 rows ----
        #pragma unroll
        for (int j = 0; j < 16; ++j) a[j] = 0.0f;
        #pragma unroll
        for (int o = 0; o < 32; ++o) {
            const float go = v[o];
            const float* wr = cw2 + o * 32 + 16 * half;
            #pragma unroll
            for (int q = 0; q < 16; ++q) a[q] = fmaf(wr[q], go, a[q]);
        }
        #pragma unroll
        for (int j = 0; j < 16; ++j) {
            int i = 16 * half + j;
            ST[(48 + i) * NP] = a[j] * sig_from_h(ST[(16 + i) * NP]);
        }
        __syncwarp();
        #pragma unroll
        for (int i = 0; i < 32; ++i) v[i] = ST[(48 + i) * NP];   // full g2

        // ---- g1 (own 8 of 16) + gy partials, pair-reduce via shfl ----
        #pragma unroll
        for (int j = 0; j < 8; ++j) a[j] = 0.0f;
        #pragma unroll
        for (int o = 0; o < 32; ++o) {
            const float go = v[o];
            const float* wr = cw1 + o * 16 + 8 * half;
            #pragma unroll
            for (int q = 0; q < 8; ++q) a[q] = fmaf(wr[q], go, a[q]);
        }
        float gy0 = 0.0f, gy1 = 0.0f;
        #pragma unroll
        for (int j = 0; j < 8; ++j) {
            int i = 8 * half + j;
            float g1 = a[j] * sig_from_h(ST[i * NP]);
            gy0 = fmaf(cw0[2*i],     g1, gy0);
            gy1 = fmaf(cw0[2*i + 1], g1, gy1);
        }
        gy0 += __shfl_xor_sync(0xffffffffu, gy0, 1);
        gy1 += __shfl_xor_sync(0xffffffffu, gy1, 1);

        y0 = fmaf(-(gy0 + ti0), DTF, y0);
        y1 = fmaf(-(gy1 + ti1), DTF, y1);
        ts += DTF;                 // same fp32 accumulation order as reference
        __syncwarp();              // protect H1 rows before next-iter rewrite
    }

    if (active) out[2 * p + half] = half ? y1 : y0;
}

extern "C" void kernel_launch(void* const* d_in, const int* in_sizes, int n_in,
                              void* d_out, int out_size)
{
    // Identify input ordering: x is uniquely 128*407 = 52096 elements.
    int xi = -1;
    for (int i = 0; i < n_in; ++i)
        if (in_sizes[i] == 128 * XROW) { xi = i; break; }

    const float *x, *W[5], *B[5], *wtp;
    if (xi == 0) {
        x = (const float*)d_in[0];
        for (int i = 0; i < 5; ++i) {
            W[i] = (const float*)d_in[1 + 2 * i];
            B[i] = (const float*)d_in[2 + 2 * i];
        }
        wtp = (const float*)d_in[11];
    } else {
        for (int i = 0; i < 5; ++i) {
            W[i] = (const float*)d_in[2 * i];
            B[i] = (const float*)d_in[2 * i + 1];
        }
        wtp = (const float*)d_in[10];
        x   = (const float*)d_in[(xi >= 0) ? xi : 11];
    }

    // D2D copies into __constant__ — capture-legal memcpy nodes, no allocation.
    cudaMemcpyToSymbolAsync(cw0, W[0],  32 * 4, 0, cudaMemcpyDeviceToDevice, 0);
    cudaMemcpyToSymbolAsync(cw1, W[1], 512 * 4, 0, cudaMemcpyDeviceToDevice, 0);
    cudaMemcpyToSymbolAsync(cw2, W[2],1024 * 4, 0, cudaMemcpyDeviceToDevice, 0);
    cudaMemcpyToSymbolAsync(cw3, W[3], 512 * 4, 0, cudaMemcpyDeviceToDevice, 0);
    cudaMemcpyToSymbolAsync(cw4, W[4],  16 * 4, 0, cudaMemcpyDeviceToDevice, 0);
    cudaMemcpyToSymbolAsync(cb0, B[0],  16 * 4, 0, cudaMemcpyDeviceToDevice, 0);
    cudaMemcpyToSymbolAsync(cb1, B[1],  32 * 4, 0, cudaMemcpyDeviceToDevice, 0);
    cudaMemcpyToSymbolAsync(cb2, B[2],  32 * 4, 0, cudaMemcpyDeviceToDevice, 0);
    cudaMemcpyToSymbolAsync(cb3, B[3],  16 * 4, 0, cudaMemcpyDeviceToDevice, 0);
    cudaMemcpyToSymbolAsync(cwt, wtp,    4 * 4, 0, cudaMemcpyDeviceToDevice, 0);

    cudaFuncSetAttribute(phinn_kernel,
                         cudaFuncAttributeMaxDynamicSharedMemorySize, SMEM_BYTES);

    float* out = (float*)d_out;
    phinn_kernel<<<NBLK, TPB, SMEM_BYTES>>>(x, out);
}

// round 8
// speedup vs baseline: 13.2394x; 13.2394x over previous
#include <cuda_runtime.h>

#define NPTS    25600     // 128 batches * 200 cells
#define XROW    407       // 2 + 400 + 5
#define NSTEPS  50
#define DTF     0.001f
#define NBLK    148
#define TPB     352       // 11 warps; 176 pairs/block
#define PAIRS_ACTIVE 173  // ceil(25600/148)

#define W2S 36            // padded row stride for w2/w3 (144B = 16 mod 128 -> conflict-free)

__device__ __forceinline__ float softplus_f(float z) {
    float e = __expf(-fabsf(z));
    return fmaxf(z, 0.0f) + __logf(1.0f + e);
}
__device__ __forceinline__ float sig_only(float z) {
    float e = __expf(-fabsf(z));
    float u = 1.0f + e;
    float r;
    asm("rcp.approx.f32 %0, %1;" : "=f"(r) : "f"(u));
    return (z >= 0.0f) ? r : e * r;
}
__device__ __forceinline__ float sig_from_h(float h) {   // sigmoid(z) = 1 - e^{-softplus(z)}
    return 1.0f - __expf(-h);
}

__global__ void __launch_bounds__(TPB, 1)
phinn_kernel(const float* __restrict__ x,
             const float* __restrict__ w0, const float* __restrict__ b0,
             const float* __restrict__ w1, const float* __restrict__ b1,
             const float* __restrict__ w2, const float* __restrict__ b2,
             const float* __restrict__ w3, const float* __restrict__ b3,
             const float* __restrict__ w4,
             const float* __restrict__ wt,
             float* __restrict__ out)
{
    // weights, physically row-interleaved so the two pair-halves' concurrent
    // reads never share a bank quad.
    __shared__ __align__(16) float sw1[32 * 16];   // phys row = 2*(o&15)+(o>>4)
    __shared__ __align__(16) float sw2[32 * W2S];  // phys row = 2*(o&15)+(o>>4)
    __shared__ __align__(16) float sw3[16 * W2S];  // phys row = 2*(o&7) +(o>>3)
    __shared__ float sw0[32], sw4[16];
    __shared__ float sb0[16], sb1[32], sb2[32], sb3[16], swt[4];

    const int tid  = threadIdx.x;
    const int pid  = tid >> 1;
    const int half = tid & 1;

    for (int i = tid; i < 512;  i += TPB) {
        int o = i >> 4, q = i & 15;
        sw1[(2 * (o & 15) + (o >> 4)) * 16 + q] = w1[i];
    }
    for (int i = tid; i < 1024; i += TPB) {
        int o = i >> 5, q = i & 31;
        sw2[(2 * (o & 15) + (o >> 4)) * W2S + q] = w2[i];
    }
    for (int i = tid; i < 512;  i += TPB) {
        int o = i >> 5, q = i & 31;
        sw3[(2 * (o & 7) + (o >> 3)) * W2S + q] = w3[i];
    }
    if (tid < 32) sw0[tid] = w0[tid];
    if (tid < 16) sw4[tid] = w4[tid];
    if (tid < 16) sb0[tid] = b0[tid];
    if (tid < 32) sb1[tid] = b1[tid];
    if (tid < 32) sb2[tid] = b2[tid];
    if (tid < 16) sb3[tid] = b3[tid];
    if (tid < 4)  swt[tid] = wt[tid];
    __syncthreads();

    const int  preal  = blockIdx.x * PAIRS_ACTIVE + pid;
    const bool active = (pid < PAIRS_ACTIVE) && (preal < NPTS);
    const int  p  = active ? preal : (NPTS - 1);      // clamp for dummies
    const int  b  = p / 200;
    const int  c  = p - b * 200;
    const float* xb = x + b * XROW;

    float y0 = xb[2 + 2 * c];
    float y1 = xb[3 + 2 * c];
    float ts = xb[0];
    const float sp0 = xb[402];
    const float tA0 = fmaf(xb[403], swt[0], xb[404] * swt[1]);
    const float tA1 = fmaf(xb[403], swt[2], xb[404] * swt[3]);
    const float tB0 = fmaf(xb[405], swt[0], xb[406] * swt[1]);
    const float tB1 = fmaf(xb[405], swt[2], xb[406] * swt[3]);

    const bool hb = (half != 0);

    #pragma unroll 1
    for (int it = 0; it < NSTEPS; ++it) {
        const bool  early = (ts < sp0);
        const float ti0 = early ? tA0 : tB0;
        const float ti1 = early ? tA1 : tB1;

        // ---- L1: own 8 of 16 ----
        float h1o[8];
        #pragma unroll
        for (int j = 0; j < 8; ++j) {
            int o = 8 * half + j;
            float z = fmaf(sw0[2*o], y0, fmaf(sw0[2*o + 1], y1, sb0[o]));
            h1o[j] = softplus_f(z);
        }
        // exchange -> v16 natural order
        float v16[16];
        #pragma unroll
        for (int j = 0; j < 8; ++j) {
            float oth = __shfl_xor_sync(0xffffffffu, h1o[j], 1);
            v16[j]     = hb ? oth    : h1o[j];
            v16[8 + j] = hb ? h1o[j] : oth;
        }

        // ---- L2: own 16 of 32 (phys row 2j+half, stride 16) ----
        float h2o[16];
        #pragma unroll
        for (int j = 0; j < 16; ++j) {
            float z = sb1[16 * half + j];
            const float4* wr = (const float4*)(sw1 + (2 * j + half) * 16);
            #pragma unroll
            for (int q = 0; q < 4; ++q) {
                float4 w = wr[q];
                z = fmaf(w.x, v16[4*q], fmaf(w.y, v16[4*q+1], fmaf(w.z, v16[4*q+2], fmaf(w.w, v16[4*q+3], z))));
            }
            h2o[j] = softplus_f(z);
        }
        float v32[32];
        #pragma unroll
        for (int j = 0; j < 16; ++j) {
            float oth = __shfl_xor_sync(0xffffffffu, h2o[j], 1);
            v32[j]      = hb ? oth    : h2o[j];
            v32[16 + j] = hb ? h2o[j] : oth;
        }

        // ---- L3: own 16 of 32 (phys row 2j+half, stride 36) ----
        float h3o[16];
        #pragma unroll
        for (int j = 0; j < 16; ++j) {
            float z = sb2[16 * half + j];
            const float4* wr = (const float4*)(sw2 + (2 * j + half) * W2S);
            #pragma unroll
            for (int q = 0; q < 8; ++q) {
                float4 w = wr[q];
                z = fmaf(w.x, v32[4*q], fmaf(w.y, v32[4*q+1], fmaf(w.z, v32[4*q+2], fmaf(w.w, v32[4*q+3], z))));
            }
            h3o[j] = softplus_f(z);
        }
        #pragma unroll
        for (int j = 0; j < 16; ++j) {
            float oth = __shfl_xor_sync(0xffffffffu, h3o[j], 1);
            v32[j]      = hb ? oth    : h3o[j];
            v32[16 + j] = hb ? h3o[j] : oth;
        }

        // ---- L4: own 8 of 16; g4 = sigmoid(z4)*w4 (phys row 2j+half) ----
        float g4o[8];
        #pragma unroll
        for (int j = 0; j < 8; ++j) {
            float z = sb3[8 * half + j];
            const float4* wr = (const float4*)(sw3 + (2 * j + half) * W2S);
            #pragma unroll
            for (int q = 0; q < 8; ++q) {
                float4 w = wr[q];
                z = fmaf(w.x, v32[4*q], fmaf(w.y, v32[4*q+1], fmaf(w.z, v32[4*q+2], fmaf(w.w, v32[4*q+3], z))));
            }
            g4o[j] = sig_only(z) * sw4[8 * half + j];
        }
        float g16[16];
        #pragma unroll
        for (int j = 0; j < 8; ++j) {
            float oth = __shfl_xor_sync(0xffffffffu, g4o[j], 1);
            g16[j]     = hb ? oth    : g4o[j];
            g16[8 + j] = hb ? g4o[j] : oth;
        }

        // ---- g3 (own cols 16*half..+15): a = w3^T g4 ----
        float a[16];
        #pragma unroll
        for (int j = 0; j < 16; ++j) a[j] = 0.0f;
        #pragma unroll
        for (int o = 0; o < 16; ++o) {
            const float go = g16[o];
            const float4* wr = (const float4*)(sw3 + (2 * (o & 7) + (o >> 3)) * W2S + 16 * half);
            #pragma unroll
            for (int q = 0; q < 4; ++q) {
                float4 w = wr[q];
                a[4*q]     = fmaf(w.x, go, a[4*q]);
                a[4*q + 1] = fmaf(w.y, go, a[4*q + 1]);
                a[4*q + 2] = fmaf(w.z, go, a[4*q + 2]);
                a[4*q + 3] = fmaf(w.w, go, a[4*q + 3]);
            }
        }
        float g3o[16];
        #pragma unroll
        for (int j = 0; j < 16; ++j) g3o[j] = a[j] * sig_from_h(h3o[j]);
        #pragma unroll
        for (int j = 0; j < 16; ++j) {
            float oth = __shfl_xor_sync(0xffffffffu, g3o[j], 1);
            v32[j]      = hb ? oth    : g3o[j];
            v32[16 + j] = hb ? g3o[j] : oth;
        }

        // ---- g2 (own cols): a = w2^T g3 ----
        #pragma unroll
        for (int j = 0; j < 16; ++j) a[j] = 0.0f;
        #pragma unroll
        for (int o = 0; o < 32; ++o) {
            const float go = v32[o];
            const float4* wr = (const float4*)(sw2 + (2 * (o & 15) + (o >> 4)) * W2S + 16 * half);
            #pragma unroll
            for (int q = 0; q < 4; ++q) {
                float4 w = wr[q];
                a[4*q]     = fmaf(w.x, go, a[4*q]);
                a[4*q + 1] = fmaf(w.y, go, a[4*q + 1]);
                a[4*q + 2] = fmaf(w.z, go, a[4*q + 2]);
                a[4*q + 3] = fmaf(w.w, go, a[4*q + 3]);
            }
        }
        float g2o[16];
        #pragma unroll
        for (int j = 0; j < 16; ++j) g2o[j] = a[j] * sig_from_h(h2o[j]);
        #pragma unroll
        for (int j = 0; j < 16; ++j) {
            float oth = __shfl_xor_sync(0xffffffffu, g2o[j], 1);
            v32[j]      = hb ? oth    : g2o[j];
            v32[16 + j] = hb ? g2o[j] : oth;
        }

        // ---- g1 (own cols 8*half..+7): a = w1^T g2 ----
        #pragma unroll
        for (int j = 0; j < 8; ++j) a[j] = 0.0f;
        #pragma unroll
        for (int o = 0; o < 32; ++o) {
            const float go = v32[o];
            const float4* wr = (const float4*)(sw1 + (2 * (o & 15) + (o >> 4)) * 16 + 8 * half);
            #pragma unroll
            for (int q = 0; q < 2; ++q) {
                float4 w = wr[q];
                a[4*q]     = fmaf(w.x, go, a[4*q]);
                a[4*q + 1] = fmaf(w.y, go, a[4*q + 1]);
                a[4*q + 2] = fmaf(w.z, go, a[4*q + 2]);
                a[4*q + 3] = fmaf(w.w, go, a[4*q + 3]);
            }
        }
        float gy0 = 0.0f, gy1 = 0.0f;
        #pragma unroll
        for (int j = 0; j < 8; ++j) {
            int i = 8 * half + j;
            float g1 = a[j] * sig_from_h(h1o[j]);
            gy0 = fmaf(sw0[2*i],     g1, gy0);
            gy1 = fmaf(sw0[2*i + 1], g1, gy1);
        }
        gy0 += __shfl_xor_sync(0xffffffffu, gy0, 1);
        gy1 += __shfl_xor_sync(0xffffffffu, gy1, 1);

        y0 = fmaf(-(gy0 + ti0), DTF, y0);
        y1 = fmaf(-(gy1 + ti1), DTF, y1);
        ts += DTF;                 // same fp32 accumulation order as reference
    }

    if (active) out[2 * p + half] = half ? y1 : y0;
}

extern "C" void kernel_launch(void* const* d_in, const int* in_sizes, int n_in,
                              void* d_out, int out_size)
{
    // Identify input ordering: x is uniquely 128*407 = 52096 elements.
    int xi = -1;
    for (int i = 0; i < n_in; ++i)
        if (in_sizes[i] == 128 * XROW) { xi = i; break; }

    const float *x, *W[5], *B[5], *wtp;
    if (xi == 0) {
        x = (const float*)d_in[0];
        for (int i = 0; i < 5; ++i) {
            W[i] = (const float*)d_in[1 + 2 * i];
            B[i] = (const float*)d_in[2 + 2 * i];
        }
        wtp = (const float*)d_in[11];
    } else {
        for (int i = 0; i < 5; ++i) {
            W[i] = (const float*)d_in[2 * i];
            B[i] = (const float*)d_in[2 * i + 1];
        }
        wtp = (const float*)d_in[10];
        x   = (const float*)d_in[(xi >= 0) ? xi : 11];
    }

    float* out = (float*)d_out;
    phinn_kernel<<<NBLK, TPB>>>(x,
                                W[0], B[0], W[1], B[1], W[2], B[2],
                                W[3], B[3], W[4], wtp, out);
}